// round 13
// baseline (speedup 1.0000x reference)
#include <cuda_runtime.h>
#include <cstdint>

#define BATCH 64
#define TLEN 160
#define HID 256
#define MAXLEN 2000

// evict-last 32-byte gather load (x/penc rows are highly reused; protect in L2).
// sm_103a requires .v4.b64 (32B) form for the .L2::evict_last qualifier.
__device__ __forceinline__ void ldg_el32(const void* p, float4& a, float4& b) {
    unsigned long long r0, r1, r2, r3;
    asm volatile("ld.global.nc.L2::evict_last.v4.b64 {%0,%1,%2,%3}, [%4];"
                 : "=l"(r0), "=l"(r1), "=l"(r2), "=l"(r3)
                 : "l"(p));
    a.x = __uint_as_float((unsigned)(r0));        a.y = __uint_as_float((unsigned)(r0 >> 32));
    a.z = __uint_as_float((unsigned)(r1));        a.w = __uint_as_float((unsigned)(r1 >> 32));
    b.x = __uint_as_float((unsigned)(r2));        b.y = __uint_as_float((unsigned)(r2 >> 32));
    b.z = __uint_as_float((unsigned)(r3));        b.w = __uint_as_float((unsigned)(r3 >> 32));
}

// R2 geometry + __stcs (the 39.4us config) + evict-last 32B gather loads.
__global__ __launch_bounds__(256) void lr_fused_kernel(
    const float* __restrict__ x,
    const float* __restrict__ penc,
    const int*   __restrict__ dur,
    float* __restrict__ out,
    float* __restrict__ pos,
    float* __restrict__ mel_out)
{
    __shared__ int s_csum[TLEN];
    __shared__ int s_tot[TLEN / 32];

    const int b    = blockIdx.y;
    const int tid  = threadIdx.x;
    const int lane = tid & 31;
    const int warp = tid >> 5;

    // ---- in-block inclusive scan of duration[b, :] ----
    int v = 0;
    if (tid < TLEN) {
        v = __ldg(&dur[b * TLEN + tid]);
#pragma unroll
        for (int off = 1; off < 32; off <<= 1) {
            int n = __shfl_up_sync(0xffffffffu, v, off);
            if (lane >= off) v += n;
        }
        if (lane == 31) s_tot[warp] = v;
    }
    __syncthreads();
    if (tid < TLEN) {
        int add = 0;
#pragma unroll
        for (int i = 0; i < TLEN / 32; ++i)
            if (i < warp) add += s_tot[i];
        s_csum[tid] = v + add;
    }
    __syncthreads();

    const int mel = s_csum[TLEN - 1];
    if (blockIdx.x == 0 && tid == 0) mel_out[b] = (float)mel;

    // ---- one warp per output frame ----
    const int f = blockIdx.x * 8 + warp;
    const bool valid = (f < mel);

    float4 o0, o1, p0, p1;
    if (valid) {
        // searchsorted(csum, f, side='right'): first idx with csum[idx] > f
        int lo = 0, hi = TLEN;
#pragma unroll 8
        while (lo < hi) {
            int mid = (lo + hi) >> 1;
            if (s_csum[mid] <= f) lo = mid + 1; else hi = mid;
        }
        int idx  = lo < (TLEN - 1) ? lo : (TLEN - 1);
        int excl = idx ? s_csum[idx - 1] : 0;
        int pw   = f - excl;

        // lane takes bytes [32*lane, 32*lane+32) of each 1KB row
        const float* xr = x + ((size_t)b * TLEN + idx) * HID + lane * 8;
        const float* pr = penc + (size_t)pw * HID + lane * 8;
        ldg_el32(xr, o0, o1);
        ldg_el32(pr, p0, p1);
    } else {
        o0 = o1 = p0 = p1 = make_float4(0.f, 0.f, 0.f, 0.f);
    }

    const size_t row = ((size_t)b * MAXLEN + f) * HID;
    float4* ow  = (float4*)(out + row) + lane * 2;
    float4* pw4 = (float4*)(pos + row) + lane * 2;
    __stcs(ow,     o0);
    __stcs(ow + 1, o1);
    __stcs(pw4,     p0);
    __stcs(pw4 + 1, p1);
}

extern "C" void kernel_launch(void* const* d_in, const int* in_sizes, int n_in,
                              void* d_out, int out_size) {
    const float* x    = (const float*)d_in[0];   // (64,160,256) f32
    const float* penc = (const float*)d_in[1];   // (2001,256) f32
    const int*   dur  = (const int*)d_in[2];     // (64,160) int32
    // d_in[3] (max_len scalar) unused — fixed at 2000

    float* out = (float*)d_out;                                   // (64,2000,256)
    float* pos = out + (size_t)BATCH * MAXLEN * HID;              // (64,2000,256)
    float* mel = out + 2 * (size_t)BATCH * MAXLEN * HID;          // (64,)

    dim3 grid(MAXLEN / 8, BATCH);
    lr_fused_kernel<<<grid, 256>>>(x, penc, dur, out, pos, mel);
}

// round 14
// speedup vs baseline: 1.4484x; 1.4484x over previous
#include <cuda_runtime.h>
#include <cstdint>

#define BATCH 64
#define TLEN 160
#define HID 256
#define MAXLEN 2000

// Champion config (R2): single fused kernel, one block = 8 output frames of
// one batch. In-block warp-scan of duration[b,:], one warp per frame, binary
// search in smem csum, 2x1KB row copies (x-gather -> out, penc-gather -> pos)
// with evict-first streaming stores (__stcs) — the only store policy that
// avoids L2 dirty-line churn across graph replays (39.4us vs 45+ for WB/WT/TMA).
__global__ __launch_bounds__(256) void lr_fused_kernel(
    const float* __restrict__ x,
    const float* __restrict__ penc,
    const int*   __restrict__ dur,
    float* __restrict__ out,
    float* __restrict__ pos,
    float* __restrict__ mel_out)
{
    __shared__ int s_csum[TLEN];
    __shared__ int s_tot[TLEN / 32];

    const int b    = blockIdx.y;
    const int tid  = threadIdx.x;
    const int lane = tid & 31;
    const int warp = tid >> 5;

    // ---- in-block inclusive scan of duration[b, :] ----
    int v = 0;
    if (tid < TLEN) {
        v = dur[b * TLEN + tid];
#pragma unroll
        for (int off = 1; off < 32; off <<= 1) {
            int n = __shfl_up_sync(0xffffffffu, v, off);
            if (lane >= off) v += n;
        }
        if (lane == 31) s_tot[warp] = v;
    }
    __syncthreads();
    if (tid < TLEN) {
        int add = 0;
#pragma unroll
        for (int i = 0; i < TLEN / 32; ++i)
            if (i < warp) add += s_tot[i];
        s_csum[tid] = v + add;
    }
    __syncthreads();

    const int mel = s_csum[TLEN - 1];
    if (blockIdx.x == 0 && tid == 0) mel_out[b] = (float)mel;

    // ---- one warp per output frame ----
    const int f = blockIdx.x * 8 + warp;
    const bool valid = (f < mel);

    float4 o0, o1, p0, p1;
    if (valid) {
        // searchsorted(csum, f, side='right'): first idx with csum[idx] > f
        int lo = 0, hi = TLEN;
#pragma unroll 8
        while (lo < hi) {
            int mid = (lo + hi) >> 1;
            if (s_csum[mid] <= f) lo = mid + 1; else hi = mid;
        }
        int idx  = lo < (TLEN - 1) ? lo : (TLEN - 1);
        int excl = idx ? s_csum[idx - 1] : 0;
        int pw   = f - excl;

        const float4* xr = (const float4*)(x + ((size_t)b * TLEN + idx) * HID);
        const float4* pr = (const float4*)(penc + (size_t)pw * HID);
        o0 = xr[lane];  o1 = xr[lane + 32];
        p0 = pr[lane];  p1 = pr[lane + 32];
    } else {
        o0 = o1 = p0 = p1 = make_float4(0.f, 0.f, 0.f, 0.f);
    }

    const size_t row = ((size_t)b * MAXLEN + f) * HID;
    float4* ow  = (float4*)(out + row);
    float4* pw4 = (float4*)(pos + row);
    __stcs(ow + lane, o0);
    __stcs(ow + lane + 32, o1);
    __stcs(pw4 + lane, p0);
    __stcs(pw4 + lane + 32, p1);
}

extern "C" void kernel_launch(void* const* d_in, const int* in_sizes, int n_in,
                              void* d_out, int out_size) {
    const float* x    = (const float*)d_in[0];   // (64,160,256) f32
    const float* penc = (const float*)d_in[1];   // (2001,256) f32
    const int*   dur  = (const int*)d_in[2];     // (64,160) int32
    // d_in[3] (max_len scalar) unused — fixed at 2000

    float* out = (float*)d_out;                                   // (64,2000,256)
    float* pos = out + (size_t)BATCH * MAXLEN * HID;              // (64,2000,256)
    float* mel = out + 2 * (size_t)BATCH * MAXLEN * HID;          // (64,)

    dim3 grid(MAXLEN / 8, BATCH);
    lr_fused_kernel<<<grid, 256>>>(x, penc, dur, out, pos, mel);
}